// round 2
// baseline (speedup 1.0000x reference)
#include <cuda_runtime.h>

#define MAXROWS (1 << 22)   // 4M rows max (B*D)
#define MAXB 2048

__device__ float g_ce[MAXROWS];
__device__ short g_lab[MAXROWS];
__device__ float g_locsum[MAXB];
__device__ int   g_npos[MAXB];
__device__ float g_loss[MAXB];

__device__ __forceinline__ float warpReduceSumF(float v) {
#pragma unroll
    for (int o = 16; o; o >>= 1) v += __shfl_down_sync(0xffffffffu, v, o);
    return v;
}
__device__ __forceinline__ int warpReduceSumI(int v) {
#pragma unroll
    for (int o = 16; o; o >>= 1) v += __shfl_down_sync(0xffffffffu, v, o);
    return v;
}
__device__ __forceinline__ float blockReduceSumF(float v, float* sh) {
    int lane = threadIdx.x & 31, wid = threadIdx.x >> 5;
    int nw = (blockDim.x + 31) >> 5;
    v = warpReduceSumF(v);
    if (lane == 0) sh[wid] = v;
    __syncthreads();
    float r = 0.f;
    if (wid == 0) {
        r = (lane < nw) ? sh[lane] : 0.f;
        r = warpReduceSumF(r);
        if (lane == 0) sh[0] = r;
    }
    __syncthreads();
    r = sh[0];
    __syncthreads();
    return r;
}
__device__ __forceinline__ int blockReduceSumI(int v, int* sh) {
    int lane = threadIdx.x & 31, wid = threadIdx.x >> 5;
    int nw = (blockDim.x + 31) >> 5;
    v = warpReduceSumI(v);
    if (lane == 0) sh[wid] = v;
    __syncthreads();
    int r = 0;
    if (wid == 0) {
        r = (lane < nw) ? sh[lane] : 0;
        r = warpReduceSumI(r);
        if (lane == 0) sh[0] = r;
    }
    __syncthreads();
    r = sh[0];
    __syncthreads();
    return r;
}

// ---------------- Kernel 1: matching + labels + loc loss (1 CTA / batch) ----
__global__ void mb_match_kernel(const float* __restrict__ loc_pred,
                                const float* __restrict__ gt_boxes,
                                const int*   __restrict__ gt_labels,
                                const float* __restrict__ dbox,
                                int D, int M)
{
    extern __shared__ unsigned char smraw[];
    const int b   = blockIdx.x;
    const int tid = threadIdx.x;
    const int T   = blockDim.x;

    size_t off = 0;
    float* s_ov  = (float*)(smraw + off); off += (size_t)D * 4;
    short* s_obj = (short*)(smraw + off); off += (size_t)D * 2;
    off = (off + 7) & ~(size_t)7;
    float* s_gt  = (float*)(smraw + off); off += (size_t)M * 16;
    int* s_glab  = (int*)  (smraw + off); off += (size_t)M * 4;
    int* s_dpg   = (int*)  (smraw + off); off += (size_t)M * 4;
    float* s_redf= (float*)(smraw + off); off += 32 * 4;
    int* s_redi  = (int*)  (smraw + off);

    const float4* db4 = (const float4*)dbox;

    for (int i = tid; i < M * 4; i += T) s_gt[i] = gt_boxes[(size_t)b * M * 4 + i];
    for (int i = tid; i < M; i += T)     s_glab[i] = gt_labels[(size_t)b * M + i];
    __syncthreads();

    // Phase A: per prior, argmax over gts (first-index tie-break)
    for (int d = tid; d < D; d += T) {
        float4 p = db4[d];
        float px1 = p.x - p.z * 0.5f, py1 = p.y - p.w * 0.5f;
        float px2 = p.x + p.z * 0.5f, py2 = p.y + p.w * 0.5f;
        float pa = (px2 - px1) * (py2 - py1);
        float best = -1.f; int bi = 0;
        for (int m = 0; m < M; m++) {
            float gx1 = s_gt[m*4+0], gy1 = s_gt[m*4+1];
            float gx2 = s_gt[m*4+2], gy2 = s_gt[m*4+3];
            float w = fmaxf(fminf(gx2, px2) - fmaxf(gx1, px1), 0.f);
            float h = fmaxf(fminf(gy2, py2) - fmaxf(gy1, py1), 0.f);
            float inter = w * h;
            float ga = (gx2 - gx1) * (gy2 - gy1);
            float iou = inter / (ga + pa - inter);
            if (iou > best) { best = iou; bi = m; }
        }
        s_ov[d]  = best;
        s_obj[d] = (short)bi;
    }

    // Phase B: per gt, argmax over priors (warp per gt, first-index)
    {
        int wid = tid >> 5, lane = tid & 31, NW = T >> 5;
        for (int m = wid; m < M; m += NW) {
            float gx1 = s_gt[m*4+0], gy1 = s_gt[m*4+1];
            float gx2 = s_gt[m*4+2], gy2 = s_gt[m*4+3];
            float ga = (gx2 - gx1) * (gy2 - gy1);
            float best = -1.f; int bd = 0;
            for (int d = lane; d < D; d += 32) {
                float4 p = db4[d];
                float px1 = p.x - p.z * 0.5f, py1 = p.y - p.w * 0.5f;
                float px2 = p.x + p.z * 0.5f, py2 = p.y + p.w * 0.5f;
                float pa = (px2 - px1) * (py2 - py1);
                float w = fmaxf(fminf(gx2, px2) - fmaxf(gx1, px1), 0.f);
                float h = fmaxf(fminf(gy2, py2) - fmaxf(gy1, py1), 0.f);
                float inter = w * h;
                float iou = inter / (ga + pa - inter);
                if (iou > best) { best = iou; bd = d; }
            }
#pragma unroll
            for (int o = 16; o; o >>= 1) {
                float ov = __shfl_down_sync(0xffffffffu, best, o);
                int   od = __shfl_down_sync(0xffffffffu, bd, o);
                if (ov > best || (ov == best && od < bd)) { best = ov; bd = od; }
            }
            if (lane == 0) s_dpg[m] = bd;
        }
    }
    __syncthreads();

    // Phase C: force-match (sequential last-write-wins in m order)
    if (tid == 0) {
        for (int m = 0; m < M; m++) {
            int dm = s_dpg[m];
            s_obj[dm] = (short)m;
            s_ov[dm]  = 1.0f;
        }
    }
    __syncthreads();

    // Phase D: labels out + loc loss over positives
    float loc_sum = 0.f;
    int npos = 0;
    for (int d = tid; d < D; d += T) {
        int m = s_obj[d];
        float ov = s_ov[d];
        int lab = (ov < 0.5f) ? 0 : s_glab[m];
        g_lab[(size_t)b * D + d] = (short)lab;

        if (lab > 0) {
            npos++;
            float gx1 = s_gt[m*4+0], gy1 = s_gt[m*4+1];
            float gx2 = s_gt[m*4+2], gy2 = s_gt[m*4+3];
            float gcx = (gx1 + gx2) * 0.5f, gcy = (gy1 + gy2) * 0.5f;
            float gw = gx2 - gx1, gh = gy2 - gy1;
            float4 p = db4[d];
            float e0 = (gcx - p.x) / (p.z / 10.0f);
            float e1 = (gcy - p.y) / (p.w / 10.0f);
            float e2 = logf(gw / p.z) * 5.0f;
            float e3 = logf(gh / p.w) * 5.0f;
            float4 lp = *(const float4*)(loc_pred + ((size_t)b * D + d) * 4);
            float dd, ad;
            dd = lp.x - e0; ad = fabsf(dd); loc_sum += (ad < 1.f) ? 0.5f*dd*dd : ad - 0.5f;
            dd = lp.y - e1; ad = fabsf(dd); loc_sum += (ad < 1.f) ? 0.5f*dd*dd : ad - 0.5f;
            dd = lp.z - e2; ad = fabsf(dd); loc_sum += (ad < 1.f) ? 0.5f*dd*dd : ad - 0.5f;
            dd = lp.w - e3; ad = fabsf(dd); loc_sum += (ad < 1.f) ? 0.5f*dd*dd : ad - 0.5f;
        }
    }

    int   n_pos = blockReduceSumI(npos, s_redi);
    float loc_b = blockReduceSumF(loc_sum, s_redf);
    if (tid == 0) {
        g_npos[b]   = n_pos;
        g_locsum[b] = loc_b;
    }
}

// ---------------- Kernel 2: per-row cross entropy (high occupancy) ----------
__global__ void mb_ce_kernel(const float* __restrict__ cls_pred,
                             long long nrows, int C)
{
    long long row = (long long)blockIdx.x * blockDim.x + threadIdx.x;
    if (row >= nrows) return;
    const float* cp = cls_pred + row * C;
    int lab = g_lab[row];

    float mx = cp[0];
    for (int c = 1; c < C; c++) mx = fmaxf(mx, cp[c]);
    float s = 0.f;
    for (int c = 0; c < C; c++) s += __expf(cp[c] - mx);
    float ce = __logf(s) - (cp[lab] - mx);
    g_ce[row] = ce;
}

// ---------------- Kernel 3: hard-negative mining + per-batch total ----------
__global__ void mb_mine_kernel(int D)
{
    extern __shared__ unsigned char smraw[];
    float* s_ce  = (float*)smraw;
    float* s_redf= (float*)(smraw + (size_t)D * 4);
    int*   s_redi= (int*)  (smraw + (size_t)D * 4 + 32 * 4);

    const int b   = blockIdx.x;
    const int tid = threadIdx.x;
    const int T   = blockDim.x;

    float conf_pos = 0.f;
    for (int d = tid; d < D; d += T) {
        float ce = g_ce[(size_t)b * D + d];
        short lab = g_lab[(size_t)b * D + d];
        if (lab > 0) { conf_pos += ce; s_ce[d] = 0.f; }
        else         { s_ce[d] = ce; }
    }
    __syncthreads();

    float conf_b = blockReduceSumF(conf_pos, s_redf);
    int n_pos = g_npos[b];

    float neg_sum = 0.f;
    int k = 3 * n_pos;
    if (k > 0) {
        unsigned thr = 0u;
        for (int bit = 30; bit >= 0; bit--) {
            unsigned cand = thr | (1u << bit);
            float cf = __uint_as_float(cand);
            int cnt = 0;
            for (int d = tid; d < D; d += T) cnt += (s_ce[d] >= cf) ? 1 : 0;
            cnt = blockReduceSumI(cnt, s_redi);
            if (cnt >= k) thr = cand;
        }
        float tf = __uint_as_float(thr);
        int cgt = 0; float sgt = 0.f;
        for (int d = tid; d < D; d += T) {
            float v = s_ce[d];
            if (v > tf) { cgt++; sgt += v; }
        }
        cgt = blockReduceSumI(cgt, s_redi);
        sgt = blockReduceSumF(sgt, s_redf);
        neg_sum = sgt + (float)(k - cgt) * tf;
    }

    if (tid == 0) g_loss[b] = conf_b + neg_sum + g_locsum[b];
}

// ---------------- Kernel 4: finalize -----------------------------------------
__global__ void mb_finalize(float* __restrict__ out, int B)
{
    __shared__ float sf[32];
    __shared__ int si[32];
    float t = 0.f; int np = 0;
    for (int i = threadIdx.x; i < B; i += blockDim.x) {
        t += g_loss[i];
        np += g_npos[i];
    }
    t  = blockReduceSumF(t, sf);
    np = blockReduceSumI(np, si);
    if (threadIdx.x == 0) {
        int nt = np > 0 ? np : 1;
        out[0] = t / (float)nt;
    }
}

extern "C" void kernel_launch(void* const* d_in, const int* in_sizes, int n_in,
                              void* d_out, int out_size)
{
    const float* loc_pred = (const float*)d_in[0];
    const float* cls_pred = (const float*)d_in[1];
    const float* gt_boxes = (const float*)d_in[2];
    const int*   gt_labels= (const int*)  d_in[3];
    const float* dbox     = (const float*)d_in[4];

    int D = in_sizes[4] / 4;
    int B = in_sizes[0] / (D * 4);
    int C = (int)((long long)in_sizes[1] / ((long long)B * (long long)D));
    int M = in_sizes[2] / (B * 4);
    long long nrows = (long long)B * D;

    // Kernel 1 smem
    size_t sm1 = 0;
    sm1 += (size_t)D * 4;
    sm1 += (size_t)D * 2;
    sm1 = (sm1 + 7) & ~(size_t)7;
    sm1 += (size_t)M * 16;
    sm1 += (size_t)M * 4;
    sm1 += (size_t)M * 4;
    sm1 += 32 * 4 + 32 * 4;
    cudaFuncSetAttribute(mb_match_kernel,
                         cudaFuncAttributeMaxDynamicSharedMemorySize, (int)sm1);

    size_t sm3 = (size_t)D * 4 + 32 * 4 + 32 * 4;
    cudaFuncSetAttribute(mb_mine_kernel,
                         cudaFuncAttributeMaxDynamicSharedMemorySize, (int)sm3);

    mb_match_kernel<<<B, 512, sm1>>>(loc_pred, gt_boxes, gt_labels, dbox, D, M);

    int ceTPB = 256;
    int ceGrid = (int)((nrows + ceTPB - 1) / ceTPB);
    mb_ce_kernel<<<ceGrid, ceTPB>>>(cls_pred, nrows, C);

    mb_mine_kernel<<<B, 512, sm3>>>(D);

    mb_finalize<<<1, 256>>>((float*)d_out, B);
}

// round 3
// speedup vs baseline: 2.8691x; 2.8691x over previous
#include <cuda_runtime.h>

#define MAXROWS (1 << 22)
#define MAXB 2048
#define MAXM 128

__device__ float2 g_pair[MAXROWS];   // (best_inter, best_den) per (b,d)
__device__ short  g_obj[MAXROWS];
__device__ float  g_ce[MAXROWS];
__device__ short  g_lab[MAXROWS];
__device__ float  g_locsum[MAXB];
__device__ int    g_npos[MAXB];
__device__ float  g_loss[MAXB];

__device__ __forceinline__ float warpReduceSumF(float v) {
#pragma unroll
    for (int o = 16; o; o >>= 1) v += __shfl_down_sync(0xffffffffu, v, o);
    return v;
}
__device__ __forceinline__ int warpReduceSumI(int v) {
#pragma unroll
    for (int o = 16; o; o >>= 1) v += __shfl_down_sync(0xffffffffu, v, o);
    return v;
}
__device__ __forceinline__ float blockReduceSumF(float v, float* sh) {
    int lane = threadIdx.x & 31, wid = threadIdx.x >> 5;
    int nw = (blockDim.x + 31) >> 5;
    v = warpReduceSumF(v);
    if (lane == 0) sh[wid] = v;
    __syncthreads();
    float r = 0.f;
    if (wid == 0) {
        r = (lane < nw) ? sh[lane] : 0.f;
        r = warpReduceSumF(r);
        if (lane == 0) sh[0] = r;
    }
    __syncthreads();
    r = sh[0];
    __syncthreads();
    return r;
}
__device__ __forceinline__ int blockReduceSumI(int v, int* sh) {
    int lane = threadIdx.x & 31, wid = threadIdx.x >> 5;
    int nw = (blockDim.x + 31) >> 5;
    v = warpReduceSumI(v);
    if (lane == 0) sh[wid] = v;
    __syncthreads();
    int r = 0;
    if (wid == 0) {
        r = (lane < nw) ? sh[lane] : 0;
        r = warpReduceSumI(r);
        if (lane == 0) sh[0] = r;
    }
    __syncthreads();
    r = sh[0];
    __syncthreads();
    return r;
}

// ---- K1: per-prior argmax over gts, full occupancy, division-free ----------
__global__ void mb_matchA_kernel(const float* __restrict__ gt_boxes,
                                 const float* __restrict__ dbox,
                                 int D, int M)
{
    __shared__ float4 s_g[MAXM];   // gt xyxy
    __shared__ float  s_a[MAXM];   // gt area
    const int b = blockIdx.y;
    const int tid = threadIdx.x;

    for (int m = tid; m < M; m += blockDim.x) {
        float4 g = ((const float4*)gt_boxes)[(size_t)b * M + m];
        s_g[m] = g;
        s_a[m] = (g.z - g.x) * (g.w - g.y);
    }
    __syncthreads();

    int d = blockIdx.x * blockDim.x + tid;
    if (d >= D) return;

    float4 p = ((const float4*)dbox)[d];
    float px1 = p.x - p.z * 0.5f, py1 = p.y - p.w * 0.5f;
    float px2 = p.x + p.z * 0.5f, py2 = p.y + p.w * 0.5f;
    float pa = (px2 - px1) * (py2 - py1);

    float binter = -1.f, bden = 1.f;
    int bi = 0;
#pragma unroll 4
    for (int m = 0; m < M; m++) {
        float4 g = s_g[m];
        float w = fmaxf(fminf(g.z, px2) - fmaxf(g.x, px1), 0.f);
        float h = fmaxf(fminf(g.w, py2) - fmaxf(g.y, py1), 0.f);
        float inter = w * h;
        float den = (s_a[m] + pa) - inter;
        // inter/den > binter/bden  <=>  inter*bden > binter*den   (den>0)
        if (inter * bden > binter * den) { binter = inter; bden = den; bi = m; }
    }
    size_t row = (size_t)b * D + d;
    g_pair[row] = make_float2(binter, bden);
    g_obj[row]  = (short)bi;
}

// ---- K2: per-gt argmax (warp per gt), force-match, labels + loc loss -------
__global__ void mb_matchBC_kernel(const float* __restrict__ loc_pred,
                                  const float* __restrict__ gt_boxes,
                                  const int*   __restrict__ gt_labels,
                                  const float* __restrict__ dbox,
                                  int D, int M)
{
    __shared__ float4 s_g[MAXM];
    __shared__ float  s_a[MAXM];
    __shared__ int    s_glab[MAXM];
    __shared__ int    s_dpg[MAXM];
    __shared__ float  s_redf[32];
    __shared__ int    s_redi[32];

    const int b = blockIdx.x;
    const int tid = threadIdx.x;
    const int T = blockDim.x;
    const int lane = tid & 31, wid = tid >> 5;
    const float4* db4 = (const float4*)dbox;

    for (int m = tid; m < M; m += T) {
        float4 g = ((const float4*)gt_boxes)[(size_t)b * M + m];
        s_g[m] = g;
        s_a[m] = (g.z - g.x) * (g.w - g.y);
        s_glab[m] = gt_labels[(size_t)b * M + m];
    }
    __syncthreads();

    // Phase B: warp per gt, argmax over priors (first-index tie-break)
    for (int m = wid; m < M; m += (T >> 5)) {
        float4 g = s_g[m];
        float ga = s_a[m];
        float binter = -1.f, bden = 1.f;
        int bd = 0;
        for (int d = lane; d < D; d += 32) {
            float4 p = db4[d];
            float px1 = p.x - p.z * 0.5f, py1 = p.y - p.w * 0.5f;
            float px2 = p.x + p.z * 0.5f, py2 = p.y + p.w * 0.5f;
            float pa = (px2 - px1) * (py2 - py1);
            float w = fmaxf(fminf(g.z, px2) - fmaxf(g.x, px1), 0.f);
            float h = fmaxf(fminf(g.w, py2) - fmaxf(g.y, py1), 0.f);
            float inter = w * h;
            float den = (ga + pa) - inter;
            if (inter * bden > binter * den) { binter = inter; bden = den; bd = d; }
        }
#pragma unroll
        for (int o = 16; o; o >>= 1) {
            float oi = __shfl_down_sync(0xffffffffu, binter, o);
            float od = __shfl_down_sync(0xffffffffu, bden, o);
            int   ox = __shfl_down_sync(0xffffffffu, bd, o);
            float c1 = oi * bden, c2 = binter * od;
            if (c1 > c2 || (c1 == c2 && ox < bd)) { binter = oi; bden = od; bd = ox; }
        }
        if (lane == 0) s_dpg[m] = bd;
    }
    __syncthreads();

    // Phase C: force-match (sequential, last-write-wins in m order)
    if (tid == 0) {
        for (int m = 0; m < M; m++) {
            size_t r = (size_t)b * D + s_dpg[m];
            g_pair[r] = make_float2(1.f, 1.f);   // iou := 1
            g_obj[r]  = (short)m;
        }
    }
    __syncthreads();

    // Phase D: labels + loc loss
    float loc_sum = 0.f;
    int npos = 0;
    for (int d = tid; d < D; d += T) {
        size_t row = (size_t)b * D + d;
        float2 pr = g_pair[row];
        int m = g_obj[row];
        // iou < 0.5  <=>  2*inter < den
        int lab = (2.f * pr.x < pr.y) ? 0 : s_glab[m];
        g_lab[row] = (short)lab;

        if (lab > 0) {
            npos++;
            float4 g = s_g[m];
            float gcx = (g.x + g.z) * 0.5f, gcy = (g.y + g.w) * 0.5f;
            float gw = g.z - g.x, gh = g.w - g.y;
            float4 p = db4[d];
            float e0 = (gcx - p.x) * 10.0f / p.z;
            float e1 = (gcy - p.y) * 10.0f / p.w;
            float e2 = logf(gw / p.z) * 5.0f;
            float e3 = logf(gh / p.w) * 5.0f;
            float4 lp = ((const float4*)loc_pred)[row];
            float dd, ad;
            dd = lp.x - e0; ad = fabsf(dd); loc_sum += (ad < 1.f) ? 0.5f*dd*dd : ad - 0.5f;
            dd = lp.y - e1; ad = fabsf(dd); loc_sum += (ad < 1.f) ? 0.5f*dd*dd : ad - 0.5f;
            dd = lp.z - e2; ad = fabsf(dd); loc_sum += (ad < 1.f) ? 0.5f*dd*dd : ad - 0.5f;
            dd = lp.w - e3; ad = fabsf(dd); loc_sum += (ad < 1.f) ? 0.5f*dd*dd : ad - 0.5f;
        }
    }
    int   n_pos = blockReduceSumI(npos, s_redi);
    float loc_b = blockReduceSumF(loc_sum, s_redf);
    if (tid == 0) { g_npos[b] = n_pos; g_locsum[b] = loc_b; }
}

// ---- K3: coalesced CE. Warp stages 32 rows x C via float4, SMEM transpose --
__global__ void mb_ce_kernel(const float* __restrict__ cls_pred,
                             long long nrows, int C)
{
    extern __shared__ float s_tile[];   // blockDim * C floats
    const int tid = threadIdx.x;
    const int lane = tid & 31, wid = tid >> 5;

    long long r0 = (long long)blockIdx.x * blockDim.x + (long long)wid * 32;
    if (r0 >= nrows) return;
    float* sw = s_tile + (size_t)wid * 32 * C;

    long long nvalid = nrows - r0;
    if (nvalid >= 32) {
        // full tile: 32*C floats = 8*C float4s, coalesced
        const float4* src = (const float4*)(cls_pred + r0 * C);
        int nf4 = 8 * C;
        for (int i = lane; i < nf4; i += 32)
            ((float4*)sw)[i] = src[i];
    } else {
        const float* src = cls_pred + r0 * C;
        int nf = (int)nvalid * C;
        for (int i = lane; i < nf; i += 32)
            sw[i] = src[i];
    }
    __syncwarp();

    long long row = r0 + lane;
    if (row >= nrows) return;
    const float* cp = sw + lane * C;   // stride C words: gcd(21,32)=1 -> no conflicts
    int lab = g_lab[row];

    float mx = cp[0];
    for (int c = 1; c < C; c++) mx = fmaxf(mx, cp[c]);
    float s = 0.f;
    for (int c = 0; c < C; c++) s += __expf(cp[c] - mx);
    g_ce[row] = __logf(s) - (cp[lab] - mx);
}

// ---- K4: hard-negative mining (bitwise top-k) + per-batch total ------------
__global__ void mb_mine_kernel(int D)
{
    extern __shared__ unsigned char smraw[];
    float* s_ce   = (float*)smraw;
    float* s_redf = (float*)(smraw + (size_t)D * 4);
    int*   s_redi = (int*)(smraw + (size_t)D * 4 + 32 * 4);

    const int b = blockIdx.x;
    const int tid = threadIdx.x;
    const int T = blockDim.x;

    float conf_pos = 0.f;
    for (int d = tid; d < D; d += T) {
        size_t row = (size_t)b * D + d;
        float ce = g_ce[row];
        short lab = g_lab[row];
        if (lab > 0) { conf_pos += ce; s_ce[d] = 0.f; }
        else         { s_ce[d] = ce; }
    }
    __syncthreads();

    float conf_b = blockReduceSumF(conf_pos, s_redf);
    int n_pos = g_npos[b];

    float neg_sum = 0.f;
    int k = 3 * n_pos;
    if (k > 0) {
        unsigned thr = 0u;
        for (int bit = 30; bit >= 0; bit--) {
            unsigned cand = thr | (1u << bit);
            float cf = __uint_as_float(cand);
            int cnt = 0;
            for (int d = tid; d < D; d += T) cnt += (s_ce[d] >= cf) ? 1 : 0;
            cnt = blockReduceSumI(cnt, s_redi);
            if (cnt >= k) thr = cand;
        }
        float tf = __uint_as_float(thr);
        int cgt = 0; float sgt = 0.f;
        for (int d = tid; d < D; d += T) {
            float v = s_ce[d];
            if (v > tf) { cgt++; sgt += v; }
        }
        cgt = blockReduceSumI(cgt, s_redi);
        sgt = blockReduceSumF(sgt, s_redf);
        neg_sum = sgt + (float)(k - cgt) * tf;
    }

    if (tid == 0) g_loss[b] = conf_b + neg_sum + g_locsum[b];
}

// ---- K5: finalize ----------------------------------------------------------
__global__ void mb_finalize(float* __restrict__ out, int B)
{
    __shared__ float sf[32];
    __shared__ int si[32];
    float t = 0.f; int np = 0;
    for (int i = threadIdx.x; i < B; i += blockDim.x) {
        t += g_loss[i];
        np += g_npos[i];
    }
    t  = blockReduceSumF(t, sf);
    np = blockReduceSumI(np, si);
    if (threadIdx.x == 0) {
        int nt = np > 0 ? np : 1;
        out[0] = t / (float)nt;
    }
}

extern "C" void kernel_launch(void* const* d_in, const int* in_sizes, int n_in,
                              void* d_out, int out_size)
{
    const float* loc_pred = (const float*)d_in[0];
    const float* cls_pred = (const float*)d_in[1];
    const float* gt_boxes = (const float*)d_in[2];
    const int*   gt_labels= (const int*)  d_in[3];
    const float* dbox     = (const float*)d_in[4];

    int D = in_sizes[4] / 4;
    int B = in_sizes[0] / (D * 4);
    int C = (int)((long long)in_sizes[1] / ((long long)B * (long long)D));
    int M = in_sizes[2] / (B * 4);
    long long nrows = (long long)B * D;

    // K1: thread-per-prior, full occupancy
    dim3 g1((D + 255) / 256, B);
    mb_matchA_kernel<<<g1, 256>>>(gt_boxes, dbox, D, M);

    // K2: per-gt argmax + force-match + labels + loc
    mb_matchBC_kernel<<<B, 1024>>>(loc_pred, gt_boxes, gt_labels, dbox, D, M);

    // K3: coalesced CE
    int ceTPB = 256;
    size_t sm3 = (size_t)ceTPB * C * sizeof(float);
    int ceGrid = (int)((nrows + ceTPB - 1) / ceTPB);
    cudaFuncSetAttribute(mb_ce_kernel,
                         cudaFuncAttributeMaxDynamicSharedMemorySize, (int)sm3);
    mb_ce_kernel<<<ceGrid, ceTPB, sm3>>>(cls_pred, nrows, C);

    // K4: mining
    size_t sm4 = (size_t)D * 4 + 32 * 4 + 32 * 4;
    cudaFuncSetAttribute(mb_mine_kernel,
                         cudaFuncAttributeMaxDynamicSharedMemorySize, (int)sm4);
    mb_mine_kernel<<<B, 1024, sm4>>>(D);

    mb_finalize<<<1, 256>>>((float*)d_out, B);
}

// round 4
// speedup vs baseline: 3.1141x; 1.0854x over previous
#include <cuda_runtime.h>

#define MAXROWS (1 << 22)
#define MAXB 2048
#define MAXM 128

__device__ float2 g_pair[MAXROWS];   // (best_inter, best_den) per (b,d)
__device__ short  g_obj[MAXROWS];
__device__ short  g_lab[MAXROWS];
__device__ float  g_locsum[MAXB];
__device__ int    g_npos[MAXB];
__device__ float  g_loss[MAXB];

__device__ __forceinline__ float warpReduceSumF(float v) {
#pragma unroll
    for (int o = 16; o; o >>= 1) v += __shfl_down_sync(0xffffffffu, v, o);
    return v;
}
__device__ __forceinline__ int warpReduceSumI(int v) {
#pragma unroll
    for (int o = 16; o; o >>= 1) v += __shfl_down_sync(0xffffffffu, v, o);
    return v;
}
__device__ __forceinline__ float blockReduceSumF(float v, float* sh) {
    int lane = threadIdx.x & 31, wid = threadIdx.x >> 5;
    int nw = (blockDim.x + 31) >> 5;
    v = warpReduceSumF(v);
    if (lane == 0) sh[wid] = v;
    __syncthreads();
    float r = 0.f;
    if (wid == 0) {
        r = (lane < nw) ? sh[lane] : 0.f;
        r = warpReduceSumF(r);
        if (lane == 0) sh[0] = r;
    }
    __syncthreads();
    r = sh[0];
    __syncthreads();
    return r;
}
__device__ __forceinline__ int blockReduceSumI(int v, int* sh) {
    int lane = threadIdx.x & 31, wid = threadIdx.x >> 5;
    int nw = (blockDim.x + 31) >> 5;
    v = warpReduceSumI(v);
    if (lane == 0) sh[wid] = v;
    __syncthreads();
    int r = 0;
    if (wid == 0) {
        r = (lane < nw) ? sh[lane] : 0;
        r = warpReduceSumI(r);
        if (lane == 0) sh[0] = r;
    }
    __syncthreads();
    r = sh[0];
    __syncthreads();
    return r;
}

// ---- K1: per-prior argmax over gts, full occupancy, division-free ----------
__global__ void mb_matchA_kernel(const float* __restrict__ gt_boxes,
                                 const float* __restrict__ dbox,
                                 int D, int M)
{
    __shared__ float4 s_g[MAXM];
    __shared__ float  s_a[MAXM];
    const int b = blockIdx.y;
    const int tid = threadIdx.x;

    for (int m = tid; m < M; m += blockDim.x) {
        float4 g = ((const float4*)gt_boxes)[(size_t)b * M + m];
        s_g[m] = g;
        s_a[m] = (g.z - g.x) * (g.w - g.y);
    }
    __syncthreads();

    int d = blockIdx.x * blockDim.x + tid;
    if (d >= D) return;

    float4 p = ((const float4*)dbox)[d];
    float px1 = p.x - p.z * 0.5f, py1 = p.y - p.w * 0.5f;
    float px2 = p.x + p.z * 0.5f, py2 = p.y + p.w * 0.5f;
    float pa = (px2 - px1) * (py2 - py1);

    float binter = -1.f, bden = 1.f;
    int bi = 0;
#pragma unroll 4
    for (int m = 0; m < M; m++) {
        float4 g = s_g[m];
        float w = fmaxf(fminf(g.z, px2) - fmaxf(g.x, px1), 0.f);
        float h = fmaxf(fminf(g.w, py2) - fmaxf(g.y, py1), 0.f);
        float inter = w * h;
        float den = (s_a[m] + pa) - inter;
        if (inter * bden > binter * den) { binter = inter; bden = den; bi = m; }
    }
    size_t row = (size_t)b * D + d;
    g_pair[row] = make_float2(binter, bden);
    g_obj[row]  = (short)bi;
}

// ---- K2: per-gt argmax (warp per gt), force-match, labels + loc loss -------
__global__ void mb_matchBC_kernel(const float* __restrict__ loc_pred,
                                  const float* __restrict__ gt_boxes,
                                  const int*   __restrict__ gt_labels,
                                  const float* __restrict__ dbox,
                                  int D, int M)
{
    __shared__ float4 s_g[MAXM];
    __shared__ float  s_a[MAXM];
    __shared__ int    s_glab[MAXM];
    __shared__ int    s_dpg[MAXM];
    __shared__ float  s_redf[32];
    __shared__ int    s_redi[32];

    const int b = blockIdx.x;
    const int tid = threadIdx.x;
    const int T = blockDim.x;
    const int lane = tid & 31, wid = tid >> 5;
    const float4* db4 = (const float4*)dbox;

    for (int m = tid; m < M; m += T) {
        float4 g = ((const float4*)gt_boxes)[(size_t)b * M + m];
        s_g[m] = g;
        s_a[m] = (g.z - g.x) * (g.w - g.y);
        s_glab[m] = gt_labels[(size_t)b * M + m];
    }
    __syncthreads();

    // Phase B: warp per gt, argmax over priors (first-index tie-break)
    for (int m = wid; m < M; m += (T >> 5)) {
        float4 g = s_g[m];
        float ga = s_a[m];
        float binter = -1.f, bden = 1.f;
        int bd = 0;
#pragma unroll 4
        for (int d = lane; d < D; d += 32) {
            float4 p = db4[d];
            float px1 = p.x - p.z * 0.5f, py1 = p.y - p.w * 0.5f;
            float px2 = p.x + p.z * 0.5f, py2 = p.y + p.w * 0.5f;
            float pa = (px2 - px1) * (py2 - py1);
            float w = fmaxf(fminf(g.z, px2) - fmaxf(g.x, px1), 0.f);
            float h = fmaxf(fminf(g.w, py2) - fmaxf(g.y, py1), 0.f);
            float inter = w * h;
            float den = (ga + pa) - inter;
            if (inter * bden > binter * den) { binter = inter; bden = den; bd = d; }
        }
#pragma unroll
        for (int o = 16; o; o >>= 1) {
            float oi = __shfl_down_sync(0xffffffffu, binter, o);
            float od = __shfl_down_sync(0xffffffffu, bden, o);
            int   ox = __shfl_down_sync(0xffffffffu, bd, o);
            float c1 = oi * bden, c2 = binter * od;
            if (c1 > c2 || (c1 == c2 && ox < bd)) { binter = oi; bden = od; bd = ox; }
        }
        if (lane == 0) s_dpg[m] = bd;
    }
    __syncthreads();

    // Phase C: force-match (sequential, last-write-wins in m order)
    if (tid == 0) {
        for (int m = 0; m < M; m++) {
            size_t r = (size_t)b * D + s_dpg[m];
            g_pair[r] = make_float2(1.f, 1.f);
            g_obj[r]  = (short)m;
        }
    }
    __syncthreads();

    // Phase D: labels + loc loss
    float loc_sum = 0.f;
    int npos = 0;
    for (int d = tid; d < D; d += T) {
        size_t row = (size_t)b * D + d;
        float2 pr = g_pair[row];
        int m = g_obj[row];
        int lab = (2.f * pr.x < pr.y) ? 0 : s_glab[m];
        g_lab[row] = (short)lab;

        if (lab > 0) {
            npos++;
            float4 g = s_g[m];
            float gcx = (g.x + g.z) * 0.5f, gcy = (g.y + g.w) * 0.5f;
            float gw = g.z - g.x, gh = g.w - g.y;
            float4 p = db4[d];
            float e0 = (gcx - p.x) * 10.0f / p.z;
            float e1 = (gcy - p.y) * 10.0f / p.w;
            float e2 = logf(gw / p.z) * 5.0f;
            float e3 = logf(gh / p.w) * 5.0f;
            float4 lp = ((const float4*)loc_pred)[row];
            float dd, ad;
            dd = lp.x - e0; ad = fabsf(dd); loc_sum += (ad < 1.f) ? 0.5f*dd*dd : ad - 0.5f;
            dd = lp.y - e1; ad = fabsf(dd); loc_sum += (ad < 1.f) ? 0.5f*dd*dd : ad - 0.5f;
            dd = lp.z - e2; ad = fabsf(dd); loc_sum += (ad < 1.f) ? 0.5f*dd*dd : ad - 0.5f;
            dd = lp.w - e3; ad = fabsf(dd); loc_sum += (ad < 1.f) ? 0.5f*dd*dd : ad - 0.5f;
        }
    }
    int   n_pos = blockReduceSumI(npos, s_redi);
    float loc_b = blockReduceSumF(loc_sum, s_redf);
    if (tid == 0) { g_npos[b] = n_pos; g_locsum[b] = loc_b; }
}

// ---- K3: fused CE + radix-select hard-negative mining (1 CTA / batch) ------
// blockDim MUST be 1024. SMEM: s_ce[D] | staging[32 warps * 32*C floats]
// (staging reused as histogram after CE) | reduce scratch.
__global__ void mb_ce_mine_kernel(const float* __restrict__ cls_pred,
                                  int D, int C)
{
    extern __shared__ unsigned char smraw[];
    float* s_ce    = (float*)smraw;
    float* s_stage = (float*)(smraw + (size_t)D * 4);
    const size_t stageBytes = (size_t)1024 * C * 4;
    float* s_redf  = (float*)(smraw + (size_t)D * 4 + stageBytes);
    int*   s_redi  = (int*)(smraw + (size_t)D * 4 + stageBytes + 128);
    int*   s_bcast = (int*)(smraw + (size_t)D * 4 + stageBytes + 256);
    int*   s_hist  = (int*)s_stage;            // 1024 ints
    int*   s_suf   = ((int*)s_stage) + 1024;   // 1024 ints

    const int b = blockIdx.x;
    const int tid = threadIdx.x;
    const int T = blockDim.x;          // 1024
    const int lane = tid & 31, w = tid >> 5;
    const int nw = T >> 5;             // 32 warps

    // ---- CE phase: warp stages 32 rows, computes ce into s_ce --------------
    float conf_pos = 0.f;
    int nt = (D + 31) >> 5;
    float* sw = s_stage + (size_t)w * 32 * C;
    for (int t = w; t < nt; t += nw) {
        int r0 = t * 32;
        int nrows_t = min(32, D - r0);
        const float* src = cls_pred + ((size_t)b * D + r0) * C;
        if (nrows_t == 32) {
            const float4* s4 = (const float4*)src;
            int nf4 = 8 * C;
            for (int i = lane; i < nf4; i += 32)
                ((float4*)sw)[i] = s4[i];
        } else {
            int nf = nrows_t * C;
            for (int i = lane; i < nf; i += 32)
                sw[i] = src[i];
        }
        __syncwarp();
        if (lane < nrows_t) {
            int r = r0 + lane;
            const float* cp = sw + lane * C;  // stride C=21 words: conflict-free
            int lab = g_lab[(size_t)b * D + r];
            float mx = cp[0];
            for (int c = 1; c < C; c++) mx = fmaxf(mx, cp[c]);
            float s = 0.f;
            for (int c = 0; c < C; c++) s += __expf(cp[c] - mx);
            float ce = __logf(s) - (cp[lab] - mx);
            if (lab > 0) { conf_pos += ce; s_ce[r] = 0.f; }
            else         { s_ce[r] = ce; }
        }
        __syncwarp();
    }
    __syncthreads();

    float conf_b = blockReduceSumF(conf_pos, s_redf);
    int n_pos = g_npos[b];
    int k = 3 * n_pos;
    if (k > D) k = D;

    // ---- Radix select: k-th largest of s_ce (all >= 0, bits value-ordered) -
    float neg_sum = 0.f;
    if (k > 0) {
        unsigned prefix = 0;
        int above = 0;
#pragma unroll
        for (int pass = 0; pass < 3; pass++) {
            int shift = 21 - pass * 10;        // 21, 11, 1
            s_hist[tid] = 0;
            __syncthreads();
            for (int d = tid; d < D; d += T) {
                unsigned v = __float_as_uint(s_ce[d]);
                if ((v >> (shift + 10)) == prefix)
                    atomicAdd(&s_hist[(v >> shift) & 1023], 1);
            }
            __syncthreads();
            // suffix scan: s_suf[i] = sum_{j>=i} hist[j]   (T == 1024)
            s_suf[tid] = s_hist[tid];
            __syncthreads();
            for (int st = 1; st < 1024; st <<= 1) {
                int add = (tid + st < 1024) ? s_suf[tid + st] : 0;
                __syncthreads();
                s_suf[tid] += add;
                __syncthreads();
            }
            int Si  = s_suf[tid];
            int Si1 = (tid < 1023) ? s_suf[tid + 1] : 0;
            if (above + Si >= k && above + Si1 < k) {
                s_bcast[0] = tid;
                s_bcast[1] = above + Si1;
            }
            __syncthreads();
            prefix = (prefix << 10) | (unsigned)s_bcast[0];
            above  = s_bcast[1];
            __syncthreads();
        }
        // final bit (bit 0)
        int c1 = 0;
        for (int d = tid; d < D; d += T) {
            unsigned v = __float_as_uint(s_ce[d]);
            if ((v >> 1) == prefix && (v & 1u)) c1++;
        }
        c1 = blockReduceSumI(c1, s_redi);
        unsigned thrbits = (above + c1 >= k) ? ((prefix << 1) | 1u) : (prefix << 1);
        float tf = __uint_as_float(thrbits);

        int cgt = 0; float sgt = 0.f;
        for (int d = tid; d < D; d += T) {
            float v = s_ce[d];
            if (v > tf) { cgt++; sgt += v; }
        }
        cgt = blockReduceSumI(cgt, s_redi);
        sgt = blockReduceSumF(sgt, s_redf);
        neg_sum = sgt + (float)(k - cgt) * tf;
    }

    if (tid == 0) g_loss[b] = conf_b + neg_sum + g_locsum[b];
}

// ---- K4: finalize ----------------------------------------------------------
__global__ void mb_finalize(float* __restrict__ out, int B)
{
    __shared__ float sf[32];
    __shared__ int si[32];
    float t = 0.f; int np = 0;
    for (int i = threadIdx.x; i < B; i += blockDim.x) {
        t += g_loss[i];
        np += g_npos[i];
    }
    t  = blockReduceSumF(t, sf);
    np = blockReduceSumI(np, si);
    if (threadIdx.x == 0) {
        int nt = np > 0 ? np : 1;
        out[0] = t / (float)nt;
    }
}

extern "C" void kernel_launch(void* const* d_in, const int* in_sizes, int n_in,
                              void* d_out, int out_size)
{
    const float* loc_pred = (const float*)d_in[0];
    const float* cls_pred = (const float*)d_in[1];
    const float* gt_boxes = (const float*)d_in[2];
    const int*   gt_labels= (const int*)  d_in[3];
    const float* dbox     = (const float*)d_in[4];

    int D = in_sizes[4] / 4;
    int B = in_sizes[0] / (D * 4);
    int C = (int)((long long)in_sizes[1] / ((long long)B * (long long)D));
    int M = in_sizes[2] / (B * 4);

    dim3 g1((D + 255) / 256, B);
    mb_matchA_kernel<<<g1, 256>>>(gt_boxes, dbox, D, M);

    mb_matchBC_kernel<<<B, 1024>>>(loc_pred, gt_boxes, gt_labels, dbox, D, M);

    // fused CE + mining
    size_t sm3 = (size_t)D * 4 + (size_t)1024 * C * 4 + 256 + 64;
    cudaFuncSetAttribute(mb_ce_mine_kernel,
                         cudaFuncAttributeMaxDynamicSharedMemorySize, (int)sm3);
    mb_ce_mine_kernel<<<B, 1024, sm3>>>(cls_pred, D, C);

    mb_finalize<<<1, 256>>>((float*)d_out, B);
}

// round 8
// speedup vs baseline: 3.6049x; 1.1576x over previous
#include <cuda_runtime.h>

#define MAXROWS (1 << 22)
#define MAXB 2048
#define MAXM 32

__device__ float g_iou[MAXROWS];
__device__ short g_obj[MAXROWS];
__device__ unsigned long long g_gtbest[MAXB * MAXM];   // zero-init; self-reset each call
__device__ float g_loss[MAXB];
__device__ int   g_npos[MAXB];
__device__ int   g_count;                              // zero-init; self-reset

__device__ __forceinline__ float warpReduceSumF(float v) {
#pragma unroll
    for (int o = 16; o; o >>= 1) v += __shfl_down_sync(0xffffffffu, v, o);
    return v;
}
__device__ __forceinline__ int warpReduceSumI(int v) {
#pragma unroll
    for (int o = 16; o; o >>= 1) v += __shfl_down_sync(0xffffffffu, v, o);
    return v;
}
__device__ __forceinline__ float blockReduceSumF(float v, float* sh) {
    int lane = threadIdx.x & 31, wid = threadIdx.x >> 5;
    int nw = (blockDim.x + 31) >> 5;
    v = warpReduceSumF(v);
    if (lane == 0) sh[wid] = v;
    __syncthreads();
    float r = 0.f;
    if (wid == 0) {
        r = (lane < nw) ? sh[lane] : 0.f;
        r = warpReduceSumF(r);
        if (lane == 0) sh[0] = r;
    }
    __syncthreads();
    r = sh[0];
    __syncthreads();
    return r;
}
__device__ __forceinline__ int blockReduceSumI(int v, int* sh) {
    int lane = threadIdx.x & 31, wid = threadIdx.x >> 5;
    int nw = (blockDim.x + 31) >> 5;
    v = warpReduceSumI(v);
    if (lane == 0) sh[wid] = v;
    __syncthreads();
    int r = 0;
    if (wid == 0) {
        r = (lane < nw) ? sh[lane] : 0;
        r = warpReduceSumI(r);
        if (lane == 0) sh[0] = r;
    }
    __syncthreads();
    r = sh[0];
    __syncthreads();
    return r;
}

// ==== K1: all M*D IoUs computed ONCE. Per-d argmax + per-m argmax. ==========
// grid (ceil(D/256), B), 256 threads. dyn smem: M*256 u64 key table.
__global__ void __launch_bounds__(256)
mb_match_kernel(const float* __restrict__ gt_boxes,
                const float* __restrict__ dbox,
                int D, int M)
{
    extern __shared__ unsigned long long s_keys[];   // [M][256]
    __shared__ float4 s_g[MAXM];
    __shared__ float  s_a[MAXM];
    __shared__ unsigned long long s_part[MAXM * 8];

    const int b = blockIdx.y;
    const int tid = threadIdx.x;

    if (tid < M) {
        float4 g = ((const float4*)gt_boxes)[(size_t)b * M + tid];
        s_g[tid] = g;
        s_a[tid] = (g.z - g.x) * (g.w - g.y);
    }
    __syncthreads();

    const int d = blockIdx.x * 256 + tid;
    const bool valid = (d < D);

    float px1 = 0.f, py1 = 0.f, px2 = 0.f, py2 = 0.f, pa = 0.f;
    if (valid) {
        float4 p = ((const float4*)dbox)[d];
        px1 = p.x - p.z * 0.5f; py1 = p.y - p.w * 0.5f;
        px2 = p.x + p.z * 0.5f; py2 = p.y + p.w * 0.5f;
        pa = (px2 - px1) * (py2 - py1);
    }
    const unsigned long long dkey = (unsigned long long)(0xFFFFFFFFu - (unsigned)d);

    float best = -1.f;
    int bi = 0;
#pragma unroll 4
    for (int m = 0; m < M; m++) {
        float4 g = s_g[m];
        float w = fmaxf(fminf(g.z, px2) - fmaxf(g.x, px1), 0.f);
        float h = fmaxf(fminf(g.w, py2) - fmaxf(g.y, py1), 0.f);
        float inter = w * h;
        float den = (s_a[m] + pa) - inter;
        float iou = valid ? __fdividef(inter, den) : -1.f;
        if (iou > best) { best = iou; bi = m; }
        // key: max-iou first, then min-d (first-index tie-break)
        unsigned long long key = valid
            ? (((unsigned long long)__float_as_uint(iou) << 32) | dkey) : 0ull;
        s_keys[m * 256 + tid] = key;
    }
    if (valid) {
        size_t row = (size_t)b * D + d;
        g_iou[row] = best;
        g_obj[row] = (short)bi;
    }
    __syncthreads();

    // per-m reduce: 8 threads per m, transposed stride (conflict-free)
    {
        int m = tid >> 3, s = tid & 7;
        if (m < M) {
            unsigned long long mx = 0ull;
            const unsigned long long* base = s_keys + (size_t)m * 256;
#pragma unroll 8
            for (int i = 0; i < 32; i++) mx = max(mx, base[s + i * 8]);
            s_part[m * 8 + s] = mx;
        }
    }
    __syncthreads();
    if (tid < M) {
        unsigned long long mx = 0ull;
#pragma unroll
        for (int i = 0; i < 8; i++) mx = max(mx, s_part[tid * 8 + i]);
        atomicMax(&g_gtbest[b * MAXM + tid], mx);
    }
}

// ==== K2: force-match + labels + loc + CE + mining + grid-level finalize ====
// 1 CTA per batch, 1024 threads. __launch_bounds__(1024,1) caps regs at 64.
// dyn smem: s_ce[D] f32 | s_stage[1024*C] f32 (reused as hist/suffix) | s_force[D] s16
__global__ void __launch_bounds__(1024, 1)
mb_loss_kernel(const float* __restrict__ cls_pred,
               const float* __restrict__ loc_pred,
               const float* __restrict__ gt_boxes,
               const int*   __restrict__ gt_labels,
               const float* __restrict__ dbox,
               float* __restrict__ out,
               int D, int M, int C, int B)
{
    extern __shared__ unsigned char smraw[];
    float* s_ce    = (float*)smraw;
    float* s_stage = (float*)(smraw + (size_t)D * 4);
    const size_t stageBytes = (size_t)1024 * C * 4;
    short* s_force = (short*)(smraw + (size_t)D * 4 + stageBytes);
    int*   s_hist  = (int*)s_stage;
    int*   s_suf   = ((int*)s_stage) + 1024;

    __shared__ float4 s_g[MAXM];
    __shared__ float  s_a[MAXM];
    __shared__ int    s_glab[MAXM];
    __shared__ int    s_dpg[MAXM];
    __shared__ float  s_redf[32];
    __shared__ int    s_redi[32];
    __shared__ int    s_bcast[2];
    __shared__ int    s_last;

    const int b = blockIdx.x;
    const int tid = threadIdx.x;
    const int T = blockDim.x;            // 1024
    const int lane = tid & 31, w = tid >> 5;
    const int nw = T >> 5;
    const float4* db4 = (const float4*)dbox;

    if (tid < M) {
        float4 g = ((const float4*)gt_boxes)[(size_t)b * M + tid];
        s_g[tid] = g;
        s_a[tid] = (g.z - g.x) * (g.w - g.y);
        s_glab[tid] = gt_labels[(size_t)b * M + tid];
        unsigned long long key = g_gtbest[b * MAXM + tid];
        s_dpg[tid] = (int)(0xFFFFFFFFu - (unsigned)(key & 0xFFFFFFFFull));
        g_gtbest[b * MAXM + tid] = 0ull;          // reset for next graph replay
    }
    for (int i = tid; i < D; i += T) s_force[i] = -1;
    __syncthreads();
    if (tid == 0) {
        for (int m = 0; m < M; m++) s_force[s_dpg[m]] = (short)m;  // last-write-wins
    }
    __syncthreads();

    // ---- CE + labels + loc, warp-staged coalesced tiles --------------------
    float conf_pos = 0.f, loc_sum = 0.f;
    int npos = 0;
    int ntiles = (D + 31) >> 5;
    float* sw = s_stage + (size_t)w * 32 * C;
    for (int t = w; t < ntiles; t += nw) {
        int r0 = t * 32;
        int nr = min(32, D - r0);
        const float* src = cls_pred + ((size_t)b * D + r0) * C;
        if (nr == 32) {
            const float4* s4 = (const float4*)src;     // r0*C*4 is 16B-aligned (32*C*4)
            int nf4 = 8 * C;
            for (int i = lane; i < nf4; i += 32)
                ((float4*)sw)[i] = s4[i];
        } else {
            int nf = nr * C;
            for (int i = lane; i < nf; i += 32)
                sw[i] = src[i];
        }
        __syncwarp();
        if (lane < nr) {
            int r = r0 + lane;
            size_t row = (size_t)b * D + r;
            int f = s_force[r];
            int m, lab;
            if (f >= 0) { m = f; lab = s_glab[m]; }
            else {
                m = g_obj[row];
                lab = (g_iou[row] < 0.5f) ? 0 : s_glab[m];
            }
            const float* cp = sw + lane * C;   // stride C=21 words: conflict-free
            float mx = cp[0];
            for (int c = 1; c < C; c++) mx = fmaxf(mx, cp[c]);
            float s = 0.f;
            for (int c = 0; c < C; c++) s += __expf(cp[c] - mx);
            float ce = __logf(s) - (cp[lab] - mx);

            if (lab > 0) {
                npos++; conf_pos += ce; s_ce[r] = 0.f;
                float4 g = s_g[m];
                float gcx = (g.x + g.z) * 0.5f, gcy = (g.y + g.w) * 0.5f;
                float gw = g.z - g.x, gh = g.w - g.y;
                float4 p = db4[r];
                float e0 = (gcx - p.x) * 10.0f / p.z;
                float e1 = (gcy - p.y) * 10.0f / p.w;
                float e2 = __logf(gw / p.z) * 5.0f;
                float e3 = __logf(gh / p.w) * 5.0f;
                float4 lp = ((const float4*)loc_pred)[row];
                float dd, ad;
                dd = lp.x - e0; ad = fabsf(dd); loc_sum += (ad < 1.f) ? 0.5f*dd*dd : ad - 0.5f;
                dd = lp.y - e1; ad = fabsf(dd); loc_sum += (ad < 1.f) ? 0.5f*dd*dd : ad - 0.5f;
                dd = lp.z - e2; ad = fabsf(dd); loc_sum += (ad < 1.f) ? 0.5f*dd*dd : ad - 0.5f;
                dd = lp.w - e3; ad = fabsf(dd); loc_sum += (ad < 1.f) ? 0.5f*dd*dd : ad - 0.5f;
            } else {
                s_ce[r] = ce;
            }
        }
        __syncwarp();
    }
    __syncthreads();

    int   n_pos  = blockReduceSumI(npos, s_redi);
    float conf_b = blockReduceSumF(conf_pos, s_redf);
    float loc_b  = blockReduceSumF(loc_sum, s_redf);

    // ---- radix select (3x10-bit + final bit) over s_ce ---------------------
    float neg_sum = 0.f;
    int k = 3 * n_pos;
    if (k > D) k = D;
    if (k > 0) {
        unsigned prefix = 0;
        int above = 0;
#pragma unroll
        for (int pass = 0; pass < 3; pass++) {
            int shift = 21 - pass * 10;          // 21, 11, 1
            s_hist[tid] = 0;
            __syncthreads();
            for (int d = tid; d < D; d += T) {
                unsigned v = __float_as_uint(s_ce[d]);
                if ((v >> (shift + 10)) == prefix)
                    atomicAdd(&s_hist[(v >> shift) & 1023], 1);
            }
            __syncthreads();
            s_suf[tid] = s_hist[tid];
            __syncthreads();
            for (int st = 1; st < 1024; st <<= 1) {
                int add = (tid + st < 1024) ? s_suf[tid + st] : 0;
                __syncthreads();
                s_suf[tid] += add;
                __syncthreads();
            }
            int Si  = s_suf[tid];
            int Si1 = (tid < 1023) ? s_suf[tid + 1] : 0;
            if (above + Si >= k && above + Si1 < k) {
                s_bcast[0] = tid;
                s_bcast[1] = above + Si1;
            }
            __syncthreads();
            prefix = (prefix << 10) | (unsigned)s_bcast[0];
            above  = s_bcast[1];
            __syncthreads();
        }
        int c1 = 0;
        for (int d = tid; d < D; d += T) {
            unsigned v = __float_as_uint(s_ce[d]);
            if ((v >> 1) == prefix && (v & 1u)) c1++;
        }
        c1 = blockReduceSumI(c1, s_redi);
        unsigned thrbits = (above + c1 >= k) ? ((prefix << 1) | 1u) : (prefix << 1);
        float tf = __uint_as_float(thrbits);

        int cgt = 0; float sgt = 0.f;
        for (int d = tid; d < D; d += T) {
            float v = s_ce[d];
            if (v > tf) { cgt++; sgt += v; }
        }
        cgt = blockReduceSumI(cgt, s_redi);
        sgt = blockReduceSumF(sgt, s_redf);
        neg_sum = sgt + (float)(k - cgt) * tf;
    }

    if (tid == 0) {
        g_loss[b] = conf_b + neg_sum + loc_b;
        g_npos[b] = n_pos;
        __threadfence();
        int done = atomicAdd(&g_count, 1);
        s_last = (done == B - 1) ? 1 : 0;
    }
    __syncthreads();

    // ---- last CTA: final reduction over batches ----------------------------
    if (s_last) {
        __threadfence();
        float tsum = 0.f; int np = 0;
        for (int i = tid; i < B; i += T) {
            tsum += g_loss[i];
            np   += g_npos[i];
        }
        tsum = blockReduceSumF(tsum, s_redf);
        np   = blockReduceSumI(np, s_redi);
        if (tid == 0) {
            int nt = np > 0 ? np : 1;
            out[0] = tsum / (float)nt;
            g_count = 0;                     // reset for next graph replay
        }
    }
}

extern "C" void kernel_launch(void* const* d_in, const int* in_sizes, int n_in,
                              void* d_out, int out_size)
{
    const float* loc_pred = (const float*)d_in[0];
    const float* cls_pred = (const float*)d_in[1];
    const float* gt_boxes = (const float*)d_in[2];
    const int*   gt_labels= (const int*)  d_in[3];
    const float* dbox     = (const float*)d_in[4];

    int D = in_sizes[4] / 4;
    int B = in_sizes[0] / (D * 4);
    int C = (int)((long long)in_sizes[1] / ((long long)B * (long long)D));
    int M = in_sizes[2] / (B * 4);

    // K1
    size_t sm1 = (size_t)M * 256 * 8;
    cudaFuncSetAttribute(mb_match_kernel,
                         cudaFuncAttributeMaxDynamicSharedMemorySize, (int)sm1);
    dim3 g1((D + 255) / 256, B);
    mb_match_kernel<<<g1, 256, sm1>>>(gt_boxes, dbox, D, M);

    // K2
    size_t sm2 = (size_t)D * 4 + (size_t)1024 * C * 4 + (size_t)D * 2;
    cudaFuncSetAttribute(mb_loss_kernel,
                         cudaFuncAttributeMaxDynamicSharedMemorySize, (int)sm2);
    mb_loss_kernel<<<B, 1024, sm2>>>(cls_pred, loc_pred, gt_boxes, gt_labels,
                                     dbox, (float*)d_out, D, M, C, B);
}